// round 9
// baseline (speedup 1.0000x reference)
#include <cuda_runtime.h>
#include <cuda_bf16.h>
#include <math.h>
#include <stdint.h>

#define DEV_INLINE __device__ __forceinline__

// ======================= PTX helpers (plain-sm_100-legal) ===================
DEV_INLINE uint32_t smem_u32(const void* p) {
    uint32_t a;
    asm("{ .reg .u64 t; cvta.to.shared.u64 t, %1; cvt.u32.u64 %0, t; }"
        : "=r"(a) : "l"(p));
    return a;
}

#define CP_ASYNC16(dst, src) \
    asm volatile("cp.async.cg.shared.global [%0], [%1], 16;" \
                 :: "r"(dst), "l"(src) : "memory")
#define CP_ASYNC_COMMIT() asm volatile("cp.async.commit_group;" ::: "memory")
#define CP_ASYNC_WAIT1()  asm volatile("cp.async.wait_group 1;" ::: "memory")

#define LDSM_X4(r, addr) \
    asm volatile("ldmatrix.sync.aligned.m8n8.x4.shared.b16 {%0,%1,%2,%3}, [%4];" \
                 : "=r"((r)[0]), "=r"((r)[1]), "=r"((r)[2]), "=r"((r)[3]) \
                 : "r"(addr))

DEV_INLINE void mma16816(float* d, const uint32_t* a, const uint32_t* b) {
    asm volatile(
        "mma.sync.aligned.m16n8k16.row.col.f32.bf16.bf16.f32 "
        "{%0,%1,%2,%3}, {%4,%5,%6,%7}, {%8,%9}, {%0,%1,%2,%3};"
        : "+f"(d[0]), "+f"(d[1]), "+f"(d[2]), "+f"(d[3])
        : "r"(a[0]), "r"(a[1]), "r"(a[2]), "r"(a[3]),
          "r"(b[0]), "r"(b[1]));
}

// ---------------- packed f32x2 helpers (attention) --------------------------
DEV_INLINE unsigned long long pk2(float x, float y) {
    unsigned long long r;
    asm("mov.b64 %0, {%1, %2};" : "=l"(r)
        : "r"(__float_as_uint(x)), "r"(__float_as_uint(y)));
    return r;
}
DEV_INLINE void upk2(unsigned long long v, float &x, float &y) {
    unsigned int a, b;
    asm("mov.b64 {%0, %1}, %2;" : "=r"(a), "=r"(b) : "l"(v));
    x = __uint_as_float(a); y = __uint_as_float(b);
}
DEV_INLINE void fma2(unsigned long long &d, unsigned long long a, unsigned long long b) {
    asm("fma.rn.f32x2 %0, %1, %2, %0;" : "+l"(d) : "l"(a), "l"(b));
}
DEV_INLINE unsigned long long mul2(unsigned long long a, unsigned long long b) {
    unsigned long long r;
    asm("mul.rn.f32x2 %0, %1, %2;" : "=l"(r) : "l"(a), "l"(b));
    return r;
}

DEV_INLINE float gelu_exact(float x) {
    return 0.5f * x * (1.0f + erff(x * 0.7071067811865476f));
}

DEV_INLINE void split2(float x, float y, uint32_t &hi, uint32_t &lo) {
    __nv_bfloat162 h;
    h.x = __float2bfloat16(x);
    h.y = __float2bfloat16(y);
    __nv_bfloat162 l;
    l.x = __float2bfloat16(x - __bfloat162float(h.x));
    l.y = __float2bfloat16(y - __bfloat162float(h.y));
    hi = *(uint32_t*)&h;
    lo = *(uint32_t*)&l;
}

// ---------------- constants ----------------
#define MROWS 4096
#define HDIM  2048
#define FFDIM 8192

// ---------------- scratch -----------------------------------------------
__device__ __align__(16) __nv_bfloat16 g_actHi[MROWS * HDIM];
__device__ __align__(16) __nv_bfloat16 g_actLo[MROWS * HDIM];
__device__ __align__(16) __nv_bfloat16 g_ffnHi[MROWS * FFDIM];
__device__ __align__(16) __nv_bfloat16 g_ffnLo[MROWS * FFDIM];
__device__ __align__(16) float g_QKV[3 * MROWS * HDIM];
__device__ __align__(16) float g_h  [MROWS * HDIM];

__device__ __align__(16) __nv_bfloat16 g_wqTh[HDIM * HDIM],  g_wqTl[HDIM * HDIM];
__device__ __align__(16) __nv_bfloat16 g_wkTh[HDIM * HDIM],  g_wkTl[HDIM * HDIM];
__device__ __align__(16) __nv_bfloat16 g_wvTh[HDIM * HDIM],  g_wvTl[HDIM * HDIM];
__device__ __align__(16) __nv_bfloat16 g_woTh[HDIM * HDIM],  g_woTl[HDIM * HDIM];
__device__ __align__(16) __nv_bfloat16 g_w1Th[FFDIM * HDIM], g_w1Tl[FFDIM * HDIM];
__device__ __align__(16) __nv_bfloat16 g_w2Th[HDIM * FFDIM], g_w2Tl[HDIM * FFDIM];

// ================== weight transpose + split ================================
__global__ __launch_bounds__(256) void transpose_split(
    const float* __restrict__ W, __nv_bfloat16* __restrict__ Th,
    __nv_bfloat16* __restrict__ Tl, int K, int N)
{
    __shared__ float t[32][33];
    const int tx = threadIdx.x, ty = threadIdx.y;
    const int n0 = blockIdx.x * 32, k0 = blockIdx.y * 32;
    #pragma unroll
    for (int i = 0; i < 4; i++)
        t[ty + i * 8][tx] = W[(size_t)(k0 + ty + i * 8) * N + n0 + tx];
    __syncthreads();
    #pragma unroll
    for (int i = 0; i < 4; i++) {
        float v = t[tx][ty + i * 8];
        __nv_bfloat16 h = __float2bfloat16(v);
        const size_t o = (size_t)(n0 + ty + i * 8) * K + k0 + tx;
        Th[o] = h;
        Tl[o] = __float2bfloat16(v - __bfloat162float(h));
    }
}

// ================== mma.sync split-bf16 GEMM body ===========================
// Tile 128x256x32, 8 warps (2m x 4n), warp tile 64x64, mma.m16n8k16 bf16,
// 3 split terms.  smem: 64B rows, XOR swizzle.  3-stage cp.async, 1 CTA/SM.
// EPI: 0 = fp32 out, 1 = GELU -> bf16 hi/lo out, 2 = +residual fp32 out.
#define ATILEB 8192                       // 128 rows * 64B
#define BTILEB 16384                      // 256 rows * 64B
#define STAGEB (2 * ATILEB + 2 * BTILEB)  // 49152
#define NSTAGE 3
#define GM_SMEM_BYTES (NSTAGE * STAGEB)   // 147456

template<int EPI>
DEV_INLINE void gemm_body(
    const __nv_bfloat16* __restrict__ Ahi, const __nv_bfloat16* __restrict__ Alo,
    const __nv_bfloat16* __restrict__ Bhi, const __nv_bfloat16* __restrict__ Blo,
    const float* __restrict__ bias, const float* __restrict__ R,
    float* __restrict__ C, __nv_bfloat16* __restrict__ Chi,
    __nv_bfloat16* __restrict__ Clo, int N, int K, int bx, int by,
    uint32_t sb)
{
    const int tid = threadIdx.x;
    const int lane = tid & 31, wid = tid >> 5;
    const int wm = wid & 1, wn = wid >> 1;

    const __nv_bfloat16* gA[2] = {
        Ahi + (size_t)(by * 128) * K,
        Alo + (size_t)(by * 128) * K };
    const __nv_bfloat16* gB[2] = {
        Bhi + (size_t)(bx * 256) * K,
        Blo + (size_t)(bx * 256) * K };

    const int ld_r = tid >> 2, ld_c = tid & 3;

    auto issue = [&](int kb) {
        const uint32_t stg = sb + (kb % NSTAGE) * STAGEB;
        #pragma unroll
        for (int t = 0; t < 2; t++) {          // A hi/lo: 128 rows
            const __nv_bfloat16* g = gA[t];
            const uint32_t tb = stg + t * ATILEB;
            #pragma unroll
            for (int i = 0; i < 2; i++) {
                const int r = ld_r + i * 64;
                const uint32_t dst = tb + r * 64 + ((ld_c ^ ((r >> 1) & 3)) * 16);
                CP_ASYNC16(dst, g + (size_t)r * K + kb * 32 + ld_c * 8);
            }
        }
        #pragma unroll
        for (int t = 0; t < 2; t++) {          // B hi/lo: 256 rows
            const __nv_bfloat16* g = gB[t];
            const uint32_t tb = stg + 2 * ATILEB + t * BTILEB;
            #pragma unroll
            for (int i = 0; i < 4; i++) {
                const int r = ld_r + i * 64;
                const uint32_t dst = tb + r * 64 + ((ld_c ^ ((r >> 1) & 3)) * 16);
                CP_ASYNC16(dst, g + (size_t)r * K + kb * 32 + ld_c * 8);
            }
        }
    };

    float acc[4][8][4];
    #pragma unroll
    for (int mt = 0; mt < 4; mt++)
        #pragma unroll
        for (int nt = 0; nt < 8; nt++)
            #pragma unroll
            for (int r = 0; r < 4; r++) acc[mt][nt][r] = 0.0f;

    issue(0); CP_ASYNC_COMMIT();
    issue(1); CP_ASYNC_COMMIT();

    const int nkb = K >> 5;
    for (int kb = 0; kb < nkb; kb++) {
        CP_ASYNC_WAIT1();
        __syncthreads();
        if (kb + 2 < nkb) issue(kb + 2);
        CP_ASYNC_COMMIT();

        const uint32_t cur = sb + (kb % NSTAGE) * STAGEB;
        #pragma unroll
        for (int ks = 0; ks < 2; ks++) {
            // B fragments: ldmatrix.x4 covers two n-tiles each
            uint32_t bh[8][2], bl[8][2];
            #pragma unroll
            for (int ntp = 0; ntp < 4; ntp++) {
                const int r = wn * 64 + ntp * 16 + ((lane >> 4) & 1) * 8 + (lane & 7);
                const int ch = ks * 2 + ((lane >> 3) & 1);
                const uint32_t ba = cur + 2 * ATILEB + r * 64
                                  + ((ch ^ ((r >> 1) & 3)) * 16);
                uint32_t t4[4];
                LDSM_X4(t4, ba);
                bh[ntp * 2][0] = t4[0]; bh[ntp * 2][1] = t4[1];
                bh[ntp * 2 + 1][0] = t4[2]; bh[ntp * 2 + 1][1] = t4[3];
                LDSM_X4(t4, ba + BTILEB);
                bl[ntp * 2][0] = t4[0]; bl[ntp * 2][1] = t4[1];
                bl[ntp * 2 + 1][0] = t4[2]; bl[ntp * 2 + 1][1] = t4[3];
            }
            #pragma unroll
            for (int mt = 0; mt < 4; mt++) {
                uint32_t ah[4], al[4];
                const int r = wm * 64 + mt * 16 + (lane & 15);
                const int ch = ks * 2 + ((lane >> 4) & 1);
                const uint32_t aa = cur + r * 64
                                  + ((ch ^ ((r >> 1) & 3)) * 16);
                LDSM_X4(ah, aa);
                LDSM_X4(al, aa + ATILEB);
                #pragma unroll
                for (int nt = 0; nt < 8; nt++) {
                    mma16816(acc[mt][nt], ah, bh[nt]);
                    mma16816(acc[mt][nt], ah, bl[nt]);
                    mma16816(acc[mt][nt], al, bh[nt]);
                }
            }
        }
    }

    // ---- epilogue ----
    #pragma unroll
    for (int mt = 0; mt < 4; mt++) {
        const int row = by * 128 + wm * 64 + mt * 16 + (lane >> 2);
        #pragma unroll
        for (int nt = 0; nt < 8; nt++) {
            const int col = bx * 256 + wn * 64 + nt * 8 + (lane & 3) * 2;
            float b0 = bias[col], b1 = bias[col + 1];
            float v0 = acc[mt][nt][0] + b0;
            float v1 = acc[mt][nt][1] + b1;
            float v2 = acc[mt][nt][2] + b0;
            float v3 = acc[mt][nt][3] + b1;
            const size_t o0 = (size_t)row * N + col;
            const size_t o1 = (size_t)(row + 8) * N + col;
            if (EPI == 1) {
                v0 = gelu_exact(v0); v1 = gelu_exact(v1);
                v2 = gelu_exact(v2); v3 = gelu_exact(v3);
                uint32_t h01, l01, h23, l23;
                split2(v0, v1, h01, l01);
                split2(v2, v3, h23, l23);
                *(uint32_t*)(Chi + o0) = h01;
                *(uint32_t*)(Clo + o0) = l01;
                *(uint32_t*)(Chi + o1) = h23;
                *(uint32_t*)(Clo + o1) = l23;
            } else {
                if (EPI == 2) {
                    float2 r0 = *(const float2*)(R + o0);
                    float2 r1 = *(const float2*)(R + o1);
                    v0 += r0.x; v1 += r0.y; v2 += r1.x; v3 += r1.y;
                }
                float2 s0; s0.x = v0; s0.y = v1;
                float2 s1; s1.x = v2; s1.y = v3;
                *(float2*)(C + o0) = s0;
                *(float2*)(C + o1) = s1;
            }
        }
    }
}

template<int EPI>
__global__ __launch_bounds__(256, 1) void gemm_mma(
    const __nv_bfloat16* __restrict__ Ahi, const __nv_bfloat16* __restrict__ Alo,
    const __nv_bfloat16* __restrict__ Bhi, const __nv_bfloat16* __restrict__ Blo,
    const float* __restrict__ bias, const float* __restrict__ R,
    float* __restrict__ C, __nv_bfloat16* __restrict__ Chi,
    __nv_bfloat16* __restrict__ Clo, int N, int K)
{
    extern __shared__ char smem[];
    gemm_body<EPI>(Ahi, Alo, Bhi, Blo, bias, R, C, Chi, Clo, N, K,
                   blockIdx.x, blockIdx.y, smem_u32(smem));
}

// fused QKV: grid (24, 32); blockIdx.x>>3 selects weight/bias/output
__global__ __launch_bounds__(256, 1) void gemm_qkv(
    const __nv_bfloat16* __restrict__ Ahi, const __nv_bfloat16* __restrict__ Alo,
    const __nv_bfloat16* __restrict__ Bh0, const __nv_bfloat16* __restrict__ Bl0,
    const __nv_bfloat16* __restrict__ Bh1, const __nv_bfloat16* __restrict__ Bl1,
    const __nv_bfloat16* __restrict__ Bh2, const __nv_bfloat16* __restrict__ Bl2,
    const float* __restrict__ b0, const float* __restrict__ b1,
    const float* __restrict__ b2, float* __restrict__ Cbase)
{
    extern __shared__ char smem[];
    const int sel = blockIdx.x >> 3;
    const int bx = blockIdx.x & 7;
    const __nv_bfloat16* Bh = (sel == 0) ? Bh0 : (sel == 1) ? Bh1 : Bh2;
    const __nv_bfloat16* Bl = (sel == 0) ? Bl0 : (sel == 1) ? Bl1 : Bl2;
    const float* bias = (sel == 0) ? b0 : (sel == 1) ? b1 : b2;
    float* C = Cbase + (size_t)sel * MROWS * HDIM;
    gemm_body<0>(Ahi, Alo, Bh, Bl, bias, nullptr, C, nullptr, nullptr,
                 HDIM, HDIM, bx, blockIdx.y, smem_u32(smem));
}

// ---------------- LayerNorm -> bf16 hi/lo -----------------------------------
__global__ __launch_bounds__(256) void ln_split(
    const float* __restrict__ x, const float* __restrict__ gamma,
    const float* __restrict__ beta,
    __nv_bfloat16* __restrict__ yh, __nv_bfloat16* __restrict__ yl)
{
    __shared__ float rs_[8], rq_[8];
    const int tid = threadIdx.x;
    const size_t row = blockIdx.x;
    const float4* xr = (const float4*)(x + row * HDIM);
    float4 v0 = xr[2 * tid];
    float4 v1 = xr[2 * tid + 1];
    float s = v0.x + v0.y + v0.z + v0.w + v1.x + v1.y + v1.z + v1.w;
    float q = v0.x*v0.x + v0.y*v0.y + v0.z*v0.z + v0.w*v0.w
            + v1.x*v1.x + v1.y*v1.y + v1.z*v1.z + v1.w*v1.w;
    #pragma unroll
    for (int o = 16; o; o >>= 1) {
        s += __shfl_xor_sync(0xffffffffu, s, o);
        q += __shfl_xor_sync(0xffffffffu, q, o);
    }
    if ((tid & 31) == 0) { rs_[tid >> 5] = s; rq_[tid >> 5] = q; }
    __syncthreads();
    s = 0.0f; q = 0.0f;
    #pragma unroll
    for (int i = 0; i < 8; i++) { s += rs_[i]; q += rq_[i]; }
    const float mean = s * (1.0f / 2048.0f);
    const float var  = q * (1.0f / 2048.0f) - mean * mean;
    const float rstd = rsqrtf(var + 1e-5f);
    const float4* gr = (const float4*)gamma;
    const float4* br = (const float4*)beta;
    float o[8];
    {
        float4 g4 = gr[2 * tid], b4 = br[2 * tid];
        o[0] = (v0.x - mean) * rstd * g4.x + b4.x;
        o[1] = (v0.y - mean) * rstd * g4.y + b4.y;
        o[2] = (v0.z - mean) * rstd * g4.z + b4.z;
        o[3] = (v0.w - mean) * rstd * g4.w + b4.w;
        g4 = gr[2 * tid + 1]; b4 = br[2 * tid + 1];
        o[4] = (v1.x - mean) * rstd * g4.x + b4.x;
        o[5] = (v1.y - mean) * rstd * g4.y + b4.y;
        o[6] = (v1.z - mean) * rstd * g4.z + b4.z;
        o[7] = (v1.w - mean) * rstd * g4.w + b4.w;
    }
    uint32_t h[4], l[4];
    split2(o[0], o[1], h[0], l[0]);
    split2(o[2], o[3], h[1], l[1]);
    split2(o[4], o[5], h[2], l[2]);
    split2(o[6], o[7], h[3], l[3]);
    uint4 hv; hv.x = h[0]; hv.y = h[1]; hv.z = h[2]; hv.w = h[3];
    uint4 lv; lv.x = l[0]; lv.y = l[1]; lv.z = l[2]; lv.w = l[3];
    *(uint4*)(yh + row * HDIM + tid * 8) = hv;
    *(uint4*)(yl + row * HDIM + tid * 8) = lv;
}

// ---------------- Causal flash attention (fp32 SIMT, bf16 hi/lo out) --------
#define ATTN_SMEM_FLOATS (128 * 65 + 128 * 64 + 64 * 128 + 64 * 65)
#define ATTN_SMEM_BYTES  (ATTN_SMEM_FLOATS * 4)

__global__ __launch_bounds__(256) void attn_kernel(
    const float* __restrict__ Qg, const float* __restrict__ Kg,
    const float* __restrict__ Vg,
    __nv_bfloat16* __restrict__ Ohi, __nv_bfloat16* __restrict__ Olo)
{
    extern __shared__ float sm[];
    float* Qt = sm;
    float* Kt = Qt + 128 * 65;
    float* Vs = Kt + 128 * 64;
    float* Pt = Vs + 64 * 128;

    const int tid = threadIdx.x;
    const int tx = tid & 15, ty = tid >> 4;
    const int qt = blockIdx.x, h = blockIdx.y, b = blockIdx.z;
    const size_t gbase = ((size_t)b * 2048) * HDIM + (size_t)h * 128;
    const int q0 = qt * 64;
    const float scale = 0.08838834764831845f;

    #pragma unroll
    for (int i = 0; i < 8; i++) {
        int f = i * 256 + tid;
        int qrow = f >> 5, d4 = f & 31;
        float4 v = *(const float4*)(Qg + gbase + (size_t)(q0 + qrow) * HDIM + d4 * 4);
        Qt[(d4 * 4 + 0) * 65 + qrow] = v.x;
        Qt[(d4 * 4 + 1) * 65 + qrow] = v.y;
        Qt[(d4 * 4 + 2) * 65 + qrow] = v.z;
        Qt[(d4 * 4 + 3) * 65 + qrow] = v.w;
    }

    unsigned long long o2[4][4];
    #pragma unroll
    for (int qi = 0; qi < 4; qi++)
        #pragma unroll
        for (int j = 0; j < 4; j++) o2[qi][j] = 0ULL;
    float m_[4], l_[4];
    #pragma unroll
    for (int qi = 0; qi < 4; qi++) { m_[qi] = -1e30f; l_[qi] = 0.0f; }

    for (int kt = 0; kt <= qt; kt++) {
        const int k0 = kt * 64;
        __syncthreads();
        #pragma unroll
        for (int i = 0; i < 8; i++) {
            int f = i * 256 + tid;
            int r = f >> 5, d4 = f & 31;
            float4 kv4 = *(const float4*)(Kg + gbase + (size_t)(k0 + r) * HDIM + d4 * 4);
            Kt[(d4 * 4 + 0) * 64 + r] = kv4.x;
            Kt[(d4 * 4 + 1) * 64 + r] = kv4.y;
            Kt[(d4 * 4 + 2) * 64 + r] = kv4.z;
            Kt[(d4 * 4 + 3) * 64 + r] = kv4.w;
            float4 vv4 = *(const float4*)(Vg + gbase + (size_t)(k0 + r) * HDIM + d4 * 4);
            *(float4*)&Vs[r * 128 + d4 * 4] = vv4;
        }
        __syncthreads();

        unsigned long long s2[4][2];
        #pragma unroll
        for (int qi = 0; qi < 4; qi++) { s2[qi][0] = 0ULL; s2[qi][1] = 0ULL; }
        #pragma unroll 4
        for (int d = 0; d < 128; d++) {
            float4 kb = *(const float4*)&Kt[d * 64 + tx * 4];
            unsigned long long kp0 = pk2(kb.x, kb.y);
            unsigned long long kp1 = pk2(kb.z, kb.w);
            #pragma unroll
            for (int qi = 0; qi < 4; qi++) {
                float a = Qt[d * 65 + ty * 4 + qi];
                unsigned long long ap = pk2(a, a);
                fma2(s2[qi][0], ap, kp0);
                fma2(s2[qi][1], ap, kp1);
            }
        }
        float sv[4][4];
        #pragma unroll
        for (int qi = 0; qi < 4; qi++) {
            upk2(s2[qi][0], sv[qi][0], sv[qi][1]);
            upk2(s2[qi][1], sv[qi][2], sv[qi][3]);
        }
        #pragma unroll
        for (int qi = 0; qi < 4; qi++)
            #pragma unroll
            for (int ki = 0; ki < 4; ki++) {
                float val = sv[qi][ki] * scale;
                if (kt == qt && (k0 + tx * 4 + ki) > (q0 + ty * 4 + qi))
                    val = -1e30f;
                sv[qi][ki] = val;
            }
        float mt[4];
        #pragma unroll
        for (int qi = 0; qi < 4; qi++)
            mt[qi] = fmaxf(fmaxf(sv[qi][0], sv[qi][1]), fmaxf(sv[qi][2], sv[qi][3]));
        #pragma unroll
        for (int o = 1; o < 16; o <<= 1)
            #pragma unroll
            for (int qi = 0; qi < 4; qi++)
                mt[qi] = fmaxf(mt[qi], __shfl_xor_sync(0xffffffffu, mt[qi], o));
        float rs[4], alpha[4];
        #pragma unroll
        for (int qi = 0; qi < 4; qi++) {
            float mn = fmaxf(m_[qi], mt[qi]);
            alpha[qi] = __expf(m_[qi] - mn);
            float r = 0.0f;
            #pragma unroll
            for (int ki = 0; ki < 4; ki++) {
                float p = __expf(sv[qi][ki] - mn);
                sv[qi][ki] = p;
                r += p;
            }
            rs[qi] = r;
            m_[qi] = mn;
        }
        #pragma unroll
        for (int o = 1; o < 16; o <<= 1)
            #pragma unroll
            for (int qi = 0; qi < 4; qi++)
                rs[qi] += __shfl_xor_sync(0xffffffffu, rs[qi], o);
        #pragma unroll
        for (int qi = 0; qi < 4; qi++) {
            l_[qi] = l_[qi] * alpha[qi] + rs[qi];
            unsigned long long alp = pk2(alpha[qi], alpha[qi]);
            #pragma unroll
            for (int j = 0; j < 4; j++) o2[qi][j] = mul2(o2[qi][j], alp);
        }
        #pragma unroll
        for (int qi = 0; qi < 4; qi++)
            #pragma unroll
            for (int ki = 0; ki < 4; ki++)
                Pt[(tx * 4 + ki) * 65 + ty * 4 + qi] = sv[qi][ki];
        __syncthreads();
        #pragma unroll 2
        for (int kv = 0; kv < 64; kv++) {
            float4 v0 = *(const float4*)&Vs[kv * 128 + tx * 8];
            float4 v1 = *(const float4*)&Vs[kv * 128 + tx * 8 + 4];
            unsigned long long vp[4] = { pk2(v0.x, v0.y), pk2(v0.z, v0.w),
                                         pk2(v1.x, v1.y), pk2(v1.z, v1.w) };
            #pragma unroll
            for (int qi = 0; qi < 4; qi++) {
                float p = Pt[kv * 65 + ty * 4 + qi];
                unsigned long long pp = pk2(p, p);
                #pragma unroll
                for (int j = 0; j < 4; j++) fma2(o2[qi][j], pp, vp[j]);
            }
        }
    }
    #pragma unroll
    for (int qi = 0; qi < 4; qi++) {
        float inv = 1.0f / l_[qi];
        unsigned long long ip = pk2(inv, inv);
        float ov[8];
        #pragma unroll
        for (int j = 0; j < 4; j++) {
            o2[qi][j] = mul2(o2[qi][j], ip);
            upk2(o2[qi][j], ov[2 * j], ov[2 * j + 1]);
        }
        uint32_t hh[4], ll[4];
        split2(ov[0], ov[1], hh[0], ll[0]);
        split2(ov[2], ov[3], hh[1], ll[1]);
        split2(ov[4], ov[5], hh[2], ll[2]);
        split2(ov[6], ov[7], hh[3], ll[3]);
        const int qrow = q0 + ty * 4 + qi;
        const size_t oo = gbase + (size_t)qrow * HDIM + tx * 8;
        uint4 hv; hv.x = hh[0]; hv.y = hh[1]; hv.z = hh[2]; hv.w = hh[3];
        uint4 lv; lv.x = ll[0]; lv.y = ll[1]; lv.z = ll[2]; lv.w = ll[3];
        *(uint4*)(Ohi + oo) = hv;
        *(uint4*)(Olo + oo) = lv;
    }
}

// ---------------- launch --------------------------------------------------
extern "C" void kernel_launch(void* const* d_in, const int* in_sizes, int n_in,
                              void* d_out, int out_size)
{
    (void)in_sizes; (void)n_in; (void)out_size;
    const float* x   = (const float*)d_in[0];
    const float* wq  = (const float*)d_in[1];
    const float* bq  = (const float*)d_in[2];
    const float* wk  = (const float*)d_in[3];
    const float* bk  = (const float*)d_in[4];
    const float* wv  = (const float*)d_in[5];
    const float* bv  = (const float*)d_in[6];
    const float* wo  = (const float*)d_in[7];
    const float* bo  = (const float*)d_in[8];
    const float* g1  = (const float*)d_in[9];
    const float* be1 = (const float*)d_in[10];
    const float* g2  = (const float*)d_in[11];
    const float* be2 = (const float*)d_in[12];
    const float* w1  = (const float*)d_in[13];
    const float* b1  = (const float*)d_in[14];
    const float* w2  = (const float*)d_in[15];
    const float* b2  = (const float*)d_in[16];
    float* out = (float*)d_out;

    __nv_bfloat16 *actHi, *actLo, *ffnHi, *ffnLo;
    float *p_QKV, *p_h;
    cudaGetSymbolAddress((void**)&actHi, g_actHi);
    cudaGetSymbolAddress((void**)&actLo, g_actLo);
    cudaGetSymbolAddress((void**)&ffnHi, g_ffnHi);
    cudaGetSymbolAddress((void**)&ffnLo, g_ffnLo);
    cudaGetSymbolAddress((void**)&p_QKV, g_QKV);
    cudaGetSymbolAddress((void**)&p_h,   g_h);

    __nv_bfloat16 *wqTh, *wqTl, *wkTh, *wkTl, *wvTh, *wvTl, *woTh, *woTl;
    __nv_bfloat16 *w1Th, *w1Tl, *w2Th, *w2Tl;
    cudaGetSymbolAddress((void**)&wqTh, g_wqTh);
    cudaGetSymbolAddress((void**)&wqTl, g_wqTl);
    cudaGetSymbolAddress((void**)&wkTh, g_wkTh);
    cudaGetSymbolAddress((void**)&wkTl, g_wkTl);
    cudaGetSymbolAddress((void**)&wvTh, g_wvTh);
    cudaGetSymbolAddress((void**)&wvTl, g_wvTl);
    cudaGetSymbolAddress((void**)&woTh, g_woTh);
    cudaGetSymbolAddress((void**)&woTl, g_woTl);
    cudaGetSymbolAddress((void**)&w1Th, g_w1Th);
    cudaGetSymbolAddress((void**)&w1Tl, g_w1Tl);
    cudaGetSymbolAddress((void**)&w2Th, g_w2Th);
    cudaGetSymbolAddress((void**)&w2Tl, g_w2Tl);

    float* p_q = p_QKV;
    float* p_k = p_QKV + (size_t)MROWS * HDIM;
    float* p_v = p_QKV + (size_t)2 * MROWS * HDIM;

    cudaFuncSetAttribute(attn_kernel,
                         cudaFuncAttributeMaxDynamicSharedMemorySize,
                         ATTN_SMEM_BYTES);
    cudaFuncSetAttribute(gemm_mma<0>,
                         cudaFuncAttributeMaxDynamicSharedMemorySize, GM_SMEM_BYTES);
    cudaFuncSetAttribute(gemm_mma<1>,
                         cudaFuncAttributeMaxDynamicSharedMemorySize, GM_SMEM_BYTES);
    cudaFuncSetAttribute(gemm_mma<2>,
                         cudaFuncAttributeMaxDynamicSharedMemorySize, GM_SMEM_BYTES);
    cudaFuncSetAttribute(gemm_qkv,
                         cudaFuncAttributeMaxDynamicSharedMemorySize, GM_SMEM_BYTES);

    const dim3 tb(32, 8);

    ln_split<<<MROWS, 256>>>(x, g1, be1, actHi, actLo);
    transpose_split<<<dim3(HDIM / 32, HDIM / 32), tb>>>(wq, wqTh, wqTl, HDIM, HDIM);
    transpose_split<<<dim3(HDIM / 32, HDIM / 32), tb>>>(wk, wkTh, wkTl, HDIM, HDIM);
    transpose_split<<<dim3(HDIM / 32, HDIM / 32), tb>>>(wv, wvTh, wvTl, HDIM, HDIM);
    transpose_split<<<dim3(HDIM / 32, HDIM / 32), tb>>>(wo, woTh, woTl, HDIM, HDIM);

    // fused QKV projection (tile 128x256)
    gemm_qkv<<<dim3(24, 32), 256, GM_SMEM_BYTES>>>(
        actHi, actLo, wqTh, wqTl, wkTh, wkTl, wvTh, wvTl, bq, bk, bv, p_QKV);

    // causal attention -> split output (overwrites LN1 act, now dead)
    attn_kernel<<<dim3(32, 16, 2), 256, ATTN_SMEM_BYTES>>>(p_q, p_k, p_v, actHi, actLo);

    // output projection + residual (h = x + attn @ wo + bo)
    gemm_mma<2><<<dim3(8, 32), 256, GM_SMEM_BYTES>>>(actHi, actLo, woTh, woTl, bo, x, p_h, nullptr, nullptr, HDIM, HDIM);

    // LN2 -> split (attn act dead)
    ln_split<<<MROWS, 256>>>(p_h, g2, be2, actHi, actLo);

    // FFN weight transposes (deferred)
    transpose_split<<<dim3(FFDIM / 32, HDIM / 32), tb>>>(w1, w1Th, w1Tl, HDIM, FFDIM);
    transpose_split<<<dim3(HDIM / 32, FFDIM / 32), tb>>>(w2, w2Th, w2Tl, FFDIM, HDIM);

    // FFN1 + GELU -> split output
    gemm_mma<1><<<dim3(32, 32), 256, GM_SMEM_BYTES>>>(actHi, actLo, w1Th, w1Tl, b1, nullptr, nullptr, ffnHi, ffnLo, FFDIM, HDIM);

    // FFN2 + residual -> final output
    gemm_mma<2><<<dim3(8, 32), 256, GM_SMEM_BYTES>>>(ffnHi, ffnLo, w2Th, w2Tl, b2, p_h, out, nullptr, nullptr, HDIM, FFDIM);
}

// round 12
// speedup vs baseline: 1.0454x; 1.0454x over previous
#include <cuda_runtime.h>
#include <cuda_bf16.h>
#include <math.h>
#include <stdint.h>

#define DEV_INLINE __device__ __forceinline__

// ======================= PTX helpers (plain-sm_100-legal) ===================
DEV_INLINE uint32_t smem_u32(const void* p) {
    uint32_t a;
    asm("{ .reg .u64 t; cvta.to.shared.u64 t, %1; cvt.u32.u64 %0, t; }"
        : "=r"(a) : "l"(p));
    return a;
}

#define CP_ASYNC16(dst, src) \
    asm volatile("cp.async.cg.shared.global [%0], [%1], 16;" \
                 :: "r"(dst), "l"(src) : "memory")
#define CP_ASYNC_COMMIT() asm volatile("cp.async.commit_group;" ::: "memory")
#define CP_ASYNC_WAIT1()  asm volatile("cp.async.wait_group 1;" ::: "memory")

#define LDSM_X4(r, addr) \
    asm volatile("ldmatrix.sync.aligned.m8n8.x4.shared.b16 {%0,%1,%2,%3}, [%4];" \
                 : "=r"((r)[0]), "=r"((r)[1]), "=r"((r)[2]), "=r"((r)[3]) \
                 : "r"(addr))

DEV_INLINE void mma16816(float* d, const uint32_t* a, const uint32_t* b) {
    asm volatile(
        "mma.sync.aligned.m16n8k16.row.col.f32.bf16.bf16.f32 "
        "{%0,%1,%2,%3}, {%4,%5,%6,%7}, {%8,%9}, {%0,%1,%2,%3};"
        : "+f"(d[0]), "+f"(d[1]), "+f"(d[2]), "+f"(d[3])
        : "r"(a[0]), "r"(a[1]), "r"(a[2]), "r"(a[3]),
          "r"(b[0]), "r"(b[1]));
}

// ---------------- packed f32x2 helpers (attention) --------------------------
DEV_INLINE unsigned long long pk2(float x, float y) {
    unsigned long long r;
    asm("mov.b64 %0, {%1, %2};" : "=l"(r)
        : "r"(__float_as_uint(x)), "r"(__float_as_uint(y)));
    return r;
}
DEV_INLINE void upk2(unsigned long long v, float &x, float &y) {
    unsigned int a, b;
    asm("mov.b64 {%0, %1}, %2;" : "=r"(a), "=r"(b) : "l"(v));
    x = __uint_as_float(a); y = __uint_as_float(b);
}
DEV_INLINE void fma2(unsigned long long &d, unsigned long long a, unsigned long long b) {
    asm("fma.rn.f32x2 %0, %1, %2, %0;" : "+l"(d) : "l"(a), "l"(b));
}
DEV_INLINE unsigned long long mul2(unsigned long long a, unsigned long long b) {
    unsigned long long r;
    asm("mul.rn.f32x2 %0, %1, %2;" : "=l"(r) : "l"(a), "l"(b));
    return r;
}

DEV_INLINE float gelu_exact(float x) {
    return 0.5f * x * (1.0f + erff(x * 0.7071067811865476f));
}

DEV_INLINE void split2(float x, float y, uint32_t &hi, uint32_t &lo) {
    __nv_bfloat162 h;
    h.x = __float2bfloat16(x);
    h.y = __float2bfloat16(y);
    __nv_bfloat162 l;
    l.x = __float2bfloat16(x - __bfloat162float(h.x));
    l.y = __float2bfloat16(y - __bfloat162float(h.y));
    hi = *(uint32_t*)&h;
    lo = *(uint32_t*)&l;
}

// ---------------- constants ----------------
#define MROWS 4096
#define HDIM  2048
#define FFDIM 8192

// ---------------- scratch -----------------------------------------------
__device__ __align__(16) __nv_bfloat16 g_actHi[MROWS * HDIM];
__device__ __align__(16) __nv_bfloat16 g_actLo[MROWS * HDIM];
__device__ __align__(16) __nv_bfloat16 g_ffnHi[MROWS * FFDIM];
__device__ __align__(16) __nv_bfloat16 g_ffnLo[MROWS * FFDIM];
__device__ __align__(16) float g_QKV[3 * MROWS * HDIM];
__device__ __align__(16) float g_h  [MROWS * HDIM];

__device__ __align__(16) __nv_bfloat16 g_wqTh[HDIM * HDIM],  g_wqTl[HDIM * HDIM];
__device__ __align__(16) __nv_bfloat16 g_wkTh[HDIM * HDIM],  g_wkTl[HDIM * HDIM];
__device__ __align__(16) __nv_bfloat16 g_wvTh[HDIM * HDIM],  g_wvTl[HDIM * HDIM];
__device__ __align__(16) __nv_bfloat16 g_woTh[HDIM * HDIM],  g_woTl[HDIM * HDIM];
__device__ __align__(16) __nv_bfloat16 g_w1Th[FFDIM * HDIM], g_w1Tl[FFDIM * HDIM];
__device__ __align__(16) __nv_bfloat16 g_w2Th[HDIM * FFDIM], g_w2Tl[HDIM * FFDIM];

// ================== weight transpose + split ================================
DEV_INLINE void transpose_body(
    const float* __restrict__ W, __nv_bfloat16* __restrict__ Th,
    __nv_bfloat16* __restrict__ Tl, int K, int N, int bx, int by)
{
    __shared__ float t[32][33];
    const int tx = threadIdx.x, ty = threadIdx.y;
    const int n0 = bx * 32, k0 = by * 32;
    #pragma unroll
    for (int i = 0; i < 4; i++)
        t[ty + i * 8][tx] = W[(size_t)(k0 + ty + i * 8) * N + n0 + tx];
    __syncthreads();
    #pragma unroll
    for (int i = 0; i < 4; i++) {
        float v = t[tx][ty + i * 8];
        __nv_bfloat16 h = __float2bfloat16(v);
        const size_t o = (size_t)(n0 + ty + i * 8) * K + k0 + tx;
        Th[o] = h;
        Tl[o] = __float2bfloat16(v - __bfloat162float(h));
    }
}

__global__ __launch_bounds__(256) void transpose_split(
    const float* __restrict__ W, __nv_bfloat16* __restrict__ Th,
    __nv_bfloat16* __restrict__ Tl, int K, int N)
{
    transpose_body(W, Th, Tl, K, N, blockIdx.x, blockIdx.y);
}

// fused transpose of 4 square HDIMxHDIM weights: blockIdx.z selects
__global__ __launch_bounds__(256) void transpose_split4(
    const float* __restrict__ W0, __nv_bfloat16* __restrict__ Th0, __nv_bfloat16* __restrict__ Tl0,
    const float* __restrict__ W1, __nv_bfloat16* __restrict__ Th1, __nv_bfloat16* __restrict__ Tl1,
    const float* __restrict__ W2, __nv_bfloat16* __restrict__ Th2, __nv_bfloat16* __restrict__ Tl2,
    const float* __restrict__ W3, __nv_bfloat16* __restrict__ Th3, __nv_bfloat16* __restrict__ Tl3)
{
    const int z = blockIdx.z;
    const float* W = (z == 0) ? W0 : (z == 1) ? W1 : (z == 2) ? W2 : W3;
    __nv_bfloat16* Th = (z == 0) ? Th0 : (z == 1) ? Th1 : (z == 2) ? Th2 : Th3;
    __nv_bfloat16* Tl = (z == 0) ? Tl0 : (z == 1) ? Tl1 : (z == 2) ? Tl2 : Tl3;
    transpose_body(W, Th, Tl, HDIM, HDIM, blockIdx.x, blockIdx.y);
}

// ================== mma.sync split-bf16 GEMM body ===========================
// Tile 128x128x32, 8 warps (2m x 4n), mma.m16n8k16 bf16, fp32 accum,
// 3 split terms.  smem: 64B rows, XOR swizzle.  3-stage cp.async, 2 CTA/SM.
// EPI: 0 = fp32 out, 1 = GELU -> bf16 hi/lo out, 2 = +residual fp32 out.
#define TILEB 8192
#define STAGEB (4 * TILEB)
#define NSTAGE 3
#define GM_SMEM_BYTES (NSTAGE * STAGEB)   // 98304

template<int EPI>
DEV_INLINE void gemm_body(
    const __nv_bfloat16* __restrict__ Ahi, const __nv_bfloat16* __restrict__ Alo,
    const __nv_bfloat16* __restrict__ Bhi, const __nv_bfloat16* __restrict__ Blo,
    const float* __restrict__ bias, const float* __restrict__ R,
    float* __restrict__ C, __nv_bfloat16* __restrict__ Chi,
    __nv_bfloat16* __restrict__ Clo, int N, int K, int bx, int by,
    uint32_t sb)
{
    const int tid = threadIdx.x;
    const int lane = tid & 31, wid = tid >> 5;
    const int wm = wid & 1, wn = wid >> 1;

    const __nv_bfloat16* gT[4] = {
        Ahi + (size_t)(by * 128) * K,
        Alo + (size_t)(by * 128) * K,
        Bhi + (size_t)(bx * 128) * K,
        Blo + (size_t)(bx * 128) * K };

    const int ld_r = tid >> 2, ld_c = tid & 3;

    auto issue = [&](int kb) {
        const uint32_t stg = sb + (kb % NSTAGE) * STAGEB;
        #pragma unroll
        for (int t = 0; t < 4; t++) {
            const __nv_bfloat16* g = gT[t];
            const uint32_t tb = stg + t * TILEB;
            #pragma unroll
            for (int i = 0; i < 2; i++) {
                const int r = ld_r + i * 64;
                const uint32_t dst = tb + r * 64 + ((ld_c ^ ((r >> 1) & 3)) * 16);
                CP_ASYNC16(dst, g + (size_t)r * K + kb * 32 + ld_c * 8);
            }
        }
    };

    float acc[4][4][4];
    #pragma unroll
    for (int mt = 0; mt < 4; mt++)
        #pragma unroll
        for (int nt = 0; nt < 4; nt++)
            #pragma unroll
            for (int r = 0; r < 4; r++) acc[mt][nt][r] = 0.0f;

    issue(0); CP_ASYNC_COMMIT();
    issue(1); CP_ASYNC_COMMIT();

    const int nkb = K >> 5;
    for (int kb = 0; kb < nkb; kb++) {
        CP_ASYNC_WAIT1();
        __syncthreads();
        if (kb + 2 < nkb) issue(kb + 2);
        CP_ASYNC_COMMIT();

        const uint32_t cur = sb + (kb % NSTAGE) * STAGEB;
        #pragma unroll
        for (int ks = 0; ks < 2; ks++) {
            // B fragments: one ldmatrix.x4 covers two n-tiles (lanes 16-31
            // address the second tile's rows)
            uint32_t bh[4][2], bl[4][2];
            #pragma unroll
            for (int ntp = 0; ntp < 2; ntp++) {
                const int r = wn * 32 + ntp * 16 + ((lane >> 4) & 1) * 8 + (lane & 7);
                const int ch = ks * 2 + ((lane >> 3) & 1);
                const uint32_t ba = cur + 2 * TILEB + r * 64
                                  + ((ch ^ ((r >> 1) & 3)) * 16);
                uint32_t t4[4];
                LDSM_X4(t4, ba);
                bh[ntp * 2][0] = t4[0]; bh[ntp * 2][1] = t4[1];
                bh[ntp * 2 + 1][0] = t4[2]; bh[ntp * 2 + 1][1] = t4[3];
                LDSM_X4(t4, ba + TILEB);
                bl[ntp * 2][0] = t4[0]; bl[ntp * 2][1] = t4[1];
                bl[ntp * 2 + 1][0] = t4[2]; bl[ntp * 2 + 1][1] = t4[3];
            }
            #pragma unroll
            for (int mt = 0; mt < 4; mt++) {
                uint32_t ah[4], al[4];
                const int r = wm * 64 + mt * 16 + (lane & 15);
                const int ch = ks * 2 + ((lane >> 4) & 1);
                const uint32_t aa = cur + r * 64
                                  + ((ch ^ ((r >> 1) & 3)) * 16);
                LDSM_X4(ah, aa);
                LDSM_X4(al, aa + TILEB);
                #pragma unroll
                for (int nt = 0; nt < 4; nt++) {
                    mma16816(acc[mt][nt], ah, bh[nt]);
                    mma16816(acc[mt][nt], ah, bl[nt]);
                    mma16816(acc[mt][nt], al, bh[nt]);
                }
            }
        }
    }

    // ---- epilogue ----
    #pragma unroll
    for (int mt = 0; mt < 4; mt++) {
        const int row = by * 128 + wm * 64 + mt * 16 + (lane >> 2);
        #pragma unroll
        for (int nt = 0; nt < 4; nt++) {
            const int col = bx * 128 + wn * 32 + nt * 8 + (lane & 3) * 2;
            float b0 = bias[col], b1 = bias[col + 1];
            float v0 = acc[mt][nt][0] + b0;
            float v1 = acc[mt][nt][1] + b1;
            float v2 = acc[mt][nt][2] + b0;
            float v3 = acc[mt][nt][3] + b1;
            const size_t o0 = (size_t)row * N + col;
            const size_t o1 = (size_t)(row + 8) * N + col;
            if (EPI == 1) {
                v0 = gelu_exact(v0); v1 = gelu_exact(v1);
                v2 = gelu_exact(v2); v3 = gelu_exact(v3);
                uint32_t h01, l01, h23, l23;
                split2(v0, v1, h01, l01);
                split2(v2, v3, h23, l23);
                *(uint32_t*)(Chi + o0) = h01;
                *(uint32_t*)(Clo + o0) = l01;
                *(uint32_t*)(Chi + o1) = h23;
                *(uint32_t*)(Clo + o1) = l23;
            } else {
                if (EPI == 2) {
                    float2 r0 = *(const float2*)(R + o0);
                    float2 r1 = *(const float2*)(R + o1);
                    v0 += r0.x; v1 += r0.y; v2 += r1.x; v3 += r1.y;
                }
                float2 s0; s0.x = v0; s0.y = v1;
                float2 s1; s1.x = v2; s1.y = v3;
                *(float2*)(C + o0) = s0;
                *(float2*)(C + o1) = s1;
            }
        }
    }
}

template<int EPI>
__global__ __launch_bounds__(256, 2) void gemm_mma(
    const __nv_bfloat16* __restrict__ Ahi, const __nv_bfloat16* __restrict__ Alo,
    const __nv_bfloat16* __restrict__ Bhi, const __nv_bfloat16* __restrict__ Blo,
    const float* __restrict__ bias, const float* __restrict__ R,
    float* __restrict__ C, __nv_bfloat16* __restrict__ Chi,
    __nv_bfloat16* __restrict__ Clo, int N, int K)
{
    extern __shared__ char smem[];
    gemm_body<EPI>(Ahi, Alo, Bhi, Blo, bias, R, C, Chi, Clo, N, K,
                   blockIdx.x, blockIdx.y, smem_u32(smem));
}

// fused QKV: grid (48, 32); blockIdx.x>>4 selects weight/bias/output
__global__ __launch_bounds__(256, 2) void gemm_qkv(
    const __nv_bfloat16* __restrict__ Ahi, const __nv_bfloat16* __restrict__ Alo,
    const __nv_bfloat16* __restrict__ Bh0, const __nv_bfloat16* __restrict__ Bl0,
    const __nv_bfloat16* __restrict__ Bh1, const __nv_bfloat16* __restrict__ Bl1,
    const __nv_bfloat16* __restrict__ Bh2, const __nv_bfloat16* __restrict__ Bl2,
    const float* __restrict__ b0, const float* __restrict__ b1,
    const float* __restrict__ b2, float* __restrict__ Cbase)
{
    extern __shared__ char smem[];
    const int sel = blockIdx.x >> 4;
    const int bx = blockIdx.x & 15;
    const __nv_bfloat16* Bh = (sel == 0) ? Bh0 : (sel == 1) ? Bh1 : Bh2;
    const __nv_bfloat16* Bl = (sel == 0) ? Bl0 : (sel == 1) ? Bl1 : Bl2;
    const float* bias = (sel == 0) ? b0 : (sel == 1) ? b1 : b2;
    float* C = Cbase + (size_t)sel * MROWS * HDIM;
    gemm_body<0>(Ahi, Alo, Bh, Bl, bias, nullptr, C, nullptr, nullptr,
                 HDIM, HDIM, bx, blockIdx.y, smem_u32(smem));
}

// ---------------- LayerNorm -> bf16 hi/lo -----------------------------------
__global__ __launch_bounds__(256) void ln_split(
    const float* __restrict__ x, const float* __restrict__ gamma,
    const float* __restrict__ beta,
    __nv_bfloat16* __restrict__ yh, __nv_bfloat16* __restrict__ yl)
{
    __shared__ float rs_[8], rq_[8];
    const int tid = threadIdx.x;
    const size_t row = blockIdx.x;
    const float4* xr = (const float4*)(x + row * HDIM);
    float4 v0 = xr[2 * tid];
    float4 v1 = xr[2 * tid + 1];
    float s = v0.x + v0.y + v0.z + v0.w + v1.x + v1.y + v1.z + v1.w;
    float q = v0.x*v0.x + v0.y*v0.y + v0.z*v0.z + v0.w*v0.w
            + v1.x*v1.x + v1.y*v1.y + v1.z*v1.z + v1.w*v1.w;
    #pragma unroll
    for (int o = 16; o; o >>= 1) {
        s += __shfl_xor_sync(0xffffffffu, s, o);
        q += __shfl_xor_sync(0xffffffffu, q, o);
    }
    if ((tid & 31) == 0) { rs_[tid >> 5] = s; rq_[tid >> 5] = q; }
    __syncthreads();
    s = 0.0f; q = 0.0f;
    #pragma unroll
    for (int i = 0; i < 8; i++) { s += rs_[i]; q += rq_[i]; }
    const float mean = s * (1.0f / 2048.0f);
    const float var  = q * (1.0f / 2048.0f) - mean * mean;
    const float rstd = rsqrtf(var + 1e-5f);
    const float4* gr = (const float4*)gamma;
    const float4* br = (const float4*)beta;
    float o[8];
    {
        float4 g4 = gr[2 * tid], b4 = br[2 * tid];
        o[0] = (v0.x - mean) * rstd * g4.x + b4.x;
        o[1] = (v0.y - mean) * rstd * g4.y + b4.y;
        o[2] = (v0.z - mean) * rstd * g4.z + b4.z;
        o[3] = (v0.w - mean) * rstd * g4.w + b4.w;
        g4 = gr[2 * tid + 1]; b4 = br[2 * tid + 1];
        o[4] = (v1.x - mean) * rstd * g4.x + b4.x;
        o[5] = (v1.y - mean) * rstd * g4.y + b4.y;
        o[6] = (v1.z - mean) * rstd * g4.z + b4.z;
        o[7] = (v1.w - mean) * rstd * g4.w + b4.w;
    }
    uint32_t h[4], l[4];
    split2(o[0], o[1], h[0], l[0]);
    split2(o[2], o[3], h[1], l[1]);
    split2(o[4], o[5], h[2], l[2]);
    split2(o[6], o[7], h[3], l[3]);
    uint4 hv; hv.x = h[0]; hv.y = h[1]; hv.z = h[2]; hv.w = h[3];
    uint4 lv; lv.x = l[0]; lv.y = l[1]; lv.z = l[2]; lv.w = l[3];
    *(uint4*)(yh + row * HDIM + tid * 8) = hv;
    *(uint4*)(yl + row * HDIM + tid * 8) = lv;
}

// ---------------- Causal flash attention (fp32 SIMT, bf16 hi/lo out) --------
#define ATTN_SMEM_FLOATS (128 * 65 + 128 * 64 + 64 * 128 + 64 * 65)
#define ATTN_SMEM_BYTES  (ATTN_SMEM_FLOATS * 4)

__global__ __launch_bounds__(256) void attn_kernel(
    const float* __restrict__ Qg, const float* __restrict__ Kg,
    const float* __restrict__ Vg,
    __nv_bfloat16* __restrict__ Ohi, __nv_bfloat16* __restrict__ Olo)
{
    extern __shared__ float sm[];
    float* Qt = sm;
    float* Kt = Qt + 128 * 65;
    float* Vs = Kt + 128 * 64;
    float* Pt = Vs + 64 * 128;

    const int tid = threadIdx.x;
    const int tx = tid & 15, ty = tid >> 4;
    const int qt = blockIdx.x, h = blockIdx.y, b = blockIdx.z;
    const size_t gbase = ((size_t)b * 2048) * HDIM + (size_t)h * 128;
    const int q0 = qt * 64;
    const float scale = 0.08838834764831845f;

    #pragma unroll
    for (int i = 0; i < 8; i++) {
        int f = i * 256 + tid;
        int qrow = f >> 5, d4 = f & 31;
        float4 v = *(const float4*)(Qg + gbase + (size_t)(q0 + qrow) * HDIM + d4 * 4);
        Qt[(d4 * 4 + 0) * 65 + qrow] = v.x;
        Qt[(d4 * 4 + 1) * 65 + qrow] = v.y;
        Qt[(d4 * 4 + 2) * 65 + qrow] = v.z;
        Qt[(d4 * 4 + 3) * 65 + qrow] = v.w;
    }

    unsigned long long o2[4][4];
    #pragma unroll
    for (int qi = 0; qi < 4; qi++)
        #pragma unroll
        for (int j = 0; j < 4; j++) o2[qi][j] = 0ULL;
    float m_[4], l_[4];
    #pragma unroll
    for (int qi = 0; qi < 4; qi++) { m_[qi] = -1e30f; l_[qi] = 0.0f; }

    for (int kt = 0; kt <= qt; kt++) {
        const int k0 = kt * 64;
        __syncthreads();
        #pragma unroll
        for (int i = 0; i < 8; i++) {
            int f = i * 256 + tid;
            int r = f >> 5, d4 = f & 31;
            float4 kv4 = *(const float4*)(Kg + gbase + (size_t)(k0 + r) * HDIM + d4 * 4);
            Kt[(d4 * 4 + 0) * 64 + r] = kv4.x;
            Kt[(d4 * 4 + 1) * 64 + r] = kv4.y;
            Kt[(d4 * 4 + 2) * 64 + r] = kv4.z;
            Kt[(d4 * 4 + 3) * 64 + r] = kv4.w;
            float4 vv4 = *(const float4*)(Vg + gbase + (size_t)(k0 + r) * HDIM + d4 * 4);
            *(float4*)&Vs[r * 128 + d4 * 4] = vv4;
        }
        __syncthreads();

        unsigned long long s2[4][2];
        #pragma unroll
        for (int qi = 0; qi < 4; qi++) { s2[qi][0] = 0ULL; s2[qi][1] = 0ULL; }
        #pragma unroll 4
        for (int d = 0; d < 128; d++) {
            float4 kb = *(const float4*)&Kt[d * 64 + tx * 4];
            unsigned long long kp0 = pk2(kb.x, kb.y);
            unsigned long long kp1 = pk2(kb.z, kb.w);
            #pragma unroll
            for (int qi = 0; qi < 4; qi++) {
                float a = Qt[d * 65 + ty * 4 + qi];
                unsigned long long ap = pk2(a, a);
                fma2(s2[qi][0], ap, kp0);
                fma2(s2[qi][1], ap, kp1);
            }
        }
        float sv[4][4];
        #pragma unroll
        for (int qi = 0; qi < 4; qi++) {
            upk2(s2[qi][0], sv[qi][0], sv[qi][1]);
            upk2(s2[qi][1], sv[qi][2], sv[qi][3]);
        }
        #pragma unroll
        for (int qi = 0; qi < 4; qi++)
            #pragma unroll
            for (int ki = 0; ki < 4; ki++) {
                float val = sv[qi][ki] * scale;
                if (kt == qt && (k0 + tx * 4 + ki) > (q0 + ty * 4 + qi))
                    val = -1e30f;
                sv[qi][ki] = val;
            }
        float mt[4];
        #pragma unroll
        for (int qi = 0; qi < 4; qi++)
            mt[qi] = fmaxf(fmaxf(sv[qi][0], sv[qi][1]), fmaxf(sv[qi][2], sv[qi][3]));
        #pragma unroll
        for (int o = 1; o < 16; o <<= 1)
            #pragma unroll
            for (int qi = 0; qi < 4; qi++)
                mt[qi] = fmaxf(mt[qi], __shfl_xor_sync(0xffffffffu, mt[qi], o));
        float rs[4], alpha[4];
        #pragma unroll
        for (int qi = 0; qi < 4; qi++) {
            float mn = fmaxf(m_[qi], mt[qi]);
            alpha[qi] = __expf(m_[qi] - mn);
            float r = 0.0f;
            #pragma unroll
            for (int ki = 0; ki < 4; ki++) {
                float p = __expf(sv[qi][ki] - mn);
                sv[qi][ki] = p;
                r += p;
            }
            rs[qi] = r;
            m_[qi] = mn;
        }
        #pragma unroll
        for (int o = 1; o < 16; o <<= 1)
            #pragma unroll
            for (int qi = 0; qi < 4; qi++)
                rs[qi] += __shfl_xor_sync(0xffffffffu, rs[qi], o);
        #pragma unroll
        for (int qi = 0; qi < 4; qi++) {
            l_[qi] = l_[qi] * alpha[qi] + rs[qi];
            unsigned long long alp = pk2(alpha[qi], alpha[qi]);
            #pragma unroll
            for (int j = 0; j < 4; j++) o2[qi][j] = mul2(o2[qi][j], alp);
        }
        #pragma unroll
        for (int qi = 0; qi < 4; qi++)
            #pragma unroll
            for (int ki = 0; ki < 4; ki++)
                Pt[(tx * 4 + ki) * 65 + ty * 4 + qi] = sv[qi][ki];
        __syncthreads();
        #pragma unroll 2
        for (int kv = 0; kv < 64; kv++) {
            float4 v0 = *(const float4*)&Vs[kv * 128 + tx * 8];
            float4 v1 = *(const float4*)&Vs[kv * 128 + tx * 8 + 4];
            unsigned long long vp[4] = { pk2(v0.x, v0.y), pk2(v0.z, v0.w),
                                         pk2(v1.x, v1.y), pk2(v1.z, v1.w) };
            #pragma unroll
            for (int qi = 0; qi < 4; qi++) {
                float p = Pt[kv * 65 + ty * 4 + qi];
                unsigned long long pp = pk2(p, p);
                #pragma unroll
                for (int j = 0; j < 4; j++) fma2(o2[qi][j], pp, vp[j]);
            }
        }
    }
    #pragma unroll
    for (int qi = 0; qi < 4; qi++) {
        float inv = 1.0f / l_[qi];
        unsigned long long ip = pk2(inv, inv);
        float ov[8];
        #pragma unroll
        for (int j = 0; j < 4; j++) {
            o2[qi][j] = mul2(o2[qi][j], ip);
            upk2(o2[qi][j], ov[2 * j], ov[2 * j + 1]);
        }
        uint32_t hh[4], ll[4];
        split2(ov[0], ov[1], hh[0], ll[0]);
        split2(ov[2], ov[3], hh[1], ll[1]);
        split2(ov[4], ov[5], hh[2], ll[2]);
        split2(ov[6], ov[7], hh[3], ll[3]);
        const int qrow = q0 + ty * 4 + qi;
        const size_t oo = gbase + (size_t)qrow * HDIM + tx * 8;
        uint4 hv; hv.x = hh[0]; hv.y = hh[1]; hv.z = hh[2]; hv.w = hh[3];
        uint4 lv; lv.x = ll[0]; lv.y = ll[1]; lv.z = ll[2]; lv.w = ll[3];
        *(uint4*)(Ohi + oo) = hv;
        *(uint4*)(Olo + oo) = lv;
    }
}

// ---------------- launch --------------------------------------------------
extern "C" void kernel_launch(void* const* d_in, const int* in_sizes, int n_in,
                              void* d_out, int out_size)
{
    (void)in_sizes; (void)n_in; (void)out_size;
    const float* x   = (const float*)d_in[0];
    const float* wq  = (const float*)d_in[1];
    const float* bq  = (const float*)d_in[2];
    const float* wk  = (const float*)d_in[3];
    const float* bk  = (const float*)d_in[4];
    const float* wv  = (const float*)d_in[5];
    const float* bv  = (const float*)d_in[6];
    const float* wo  = (const float*)d_in[7];
    const float* bo  = (const float*)d_in[8];
    const float* g1  = (const float*)d_in[9];
    const float* be1 = (const float*)d_in[10];
    const float* g2  = (const float*)d_in[11];
    const float* be2 = (const float*)d_in[12];
    const float* w1  = (const float*)d_in[13];
    const float* b1  = (const float*)d_in[14];
    const float* w2  = (const float*)d_in[15];
    const float* b2  = (const float*)d_in[16];
    float* out = (float*)d_out;

    __nv_bfloat16 *actHi, *actLo, *ffnHi, *ffnLo;
    float *p_QKV, *p_h;
    cudaGetSymbolAddress((void**)&actHi, g_actHi);
    cudaGetSymbolAddress((void**)&actLo, g_actLo);
    cudaGetSymbolAddress((void**)&ffnHi, g_ffnHi);
    cudaGetSymbolAddress((void**)&ffnLo, g_ffnLo);
    cudaGetSymbolAddress((void**)&p_QKV, g_QKV);
    cudaGetSymbolAddress((void**)&p_h,   g_h);

    __nv_bfloat16 *wqTh, *wqTl, *wkTh, *wkTl, *wvTh, *wvTl, *woTh, *woTl;
    __nv_bfloat16 *w1Th, *w1Tl, *w2Th, *w2Tl;
    cudaGetSymbolAddress((void**)&wqTh, g_wqTh);
    cudaGetSymbolAddress((void**)&wqTl, g_wqTl);
    cudaGetSymbolAddress((void**)&wkTh, g_wkTh);
    cudaGetSymbolAddress((void**)&wkTl, g_wkTl);
    cudaGetSymbolAddress((void**)&wvTh, g_wvTh);
    cudaGetSymbolAddress((void**)&wvTl, g_wvTl);
    cudaGetSymbolAddress((void**)&woTh, g_woTh);
    cudaGetSymbolAddress((void**)&woTl, g_woTl);
    cudaGetSymbolAddress((void**)&w1Th, g_w1Th);
    cudaGetSymbolAddress((void**)&w1Tl, g_w1Tl);
    cudaGetSymbolAddress((void**)&w2Th, g_w2Th);
    cudaGetSymbolAddress((void**)&w2Tl, g_w2Tl);

    float* p_q = p_QKV;
    float* p_k = p_QKV + (size_t)MROWS * HDIM;
    float* p_v = p_QKV + (size_t)2 * MROWS * HDIM;

    cudaFuncSetAttribute(attn_kernel,
                         cudaFuncAttributeMaxDynamicSharedMemorySize,
                         ATTN_SMEM_BYTES);
    cudaFuncSetAttribute(gemm_mma<0>,
                         cudaFuncAttributeMaxDynamicSharedMemorySize, GM_SMEM_BYTES);
    cudaFuncSetAttribute(gemm_mma<1>,
                         cudaFuncAttributeMaxDynamicSharedMemorySize, GM_SMEM_BYTES);
    cudaFuncSetAttribute(gemm_mma<2>,
                         cudaFuncAttributeMaxDynamicSharedMemorySize, GM_SMEM_BYTES);
    cudaFuncSetAttribute(gemm_qkv,
                         cudaFuncAttributeMaxDynamicSharedMemorySize, GM_SMEM_BYTES);

    const dim3 tb(32, 8);

    ln_split<<<MROWS, 256>>>(x, g1, be1, actHi, actLo);

    // fused transpose of wq/wk/wv/wo (one launch, blockIdx.z selects)
    transpose_split4<<<dim3(HDIM / 32, HDIM / 32, 4), tb>>>(
        wq, wqTh, wqTl, wk, wkTh, wkTl, wv, wvTh, wvTl, wo, woTh, woTl);

    // fused QKV projection
    gemm_qkv<<<dim3(48, 32), 256, GM_SMEM_BYTES>>>(
        actHi, actLo, wqTh, wqTl, wkTh, wkTl, wvTh, wvTl, bq, bk, bv, p_QKV);

    // causal attention -> split output (overwrites LN1 act, now dead)
    attn_kernel<<<dim3(32, 16, 2), 256, ATTN_SMEM_BYTES>>>(p_q, p_k, p_v, actHi, actLo);

    // output projection + residual (h = x + attn @ wo + bo)
    gemm_mma<2><<<dim3(16, 32), 256, GM_SMEM_BYTES>>>(actHi, actLo, woTh, woTl, bo, x, p_h, nullptr, nullptr, HDIM, HDIM);

    // LN2 -> split (attn act dead)
    ln_split<<<MROWS, 256>>>(p_h, g2, be2, actHi, actLo);

    // FFN weight transposes (deferred)
    transpose_split<<<dim3(FFDIM / 32, HDIM / 32), tb>>>(w1, w1Th, w1Tl, HDIM, FFDIM);
    transpose_split<<<dim3(HDIM / 32, FFDIM / 32), tb>>>(w2, w2Th, w2Tl, FFDIM, HDIM);

    // FFN1 + GELU -> split output
    gemm_mma<1><<<dim3(64, 32), 256, GM_SMEM_BYTES>>>(actHi, actLo, w1Th, w1Tl, b1, nullptr, nullptr, ffnHi, ffnLo, FFDIM, HDIM);

    // FFN2 + residual -> final output
    gemm_mma<2><<<dim3(16, 32), 256, GM_SMEM_BYTES>>>(ffnHi, ffnLo, w2Th, w2Tl, b2, p_h, out, nullptr, nullptr, HDIM, FFDIM);
}

// round 14
// speedup vs baseline: 1.0485x; 1.0030x over previous
#include <cuda_runtime.h>
#include <cuda_bf16.h>
#include <math.h>
#include <stdint.h>

#define DEV_INLINE __device__ __forceinline__

// ======================= PTX helpers (plain-sm_100-legal) ===================
DEV_INLINE uint32_t smem_u32(const void* p) {
    uint32_t a;
    asm("{ .reg .u64 t; cvta.to.shared.u64 t, %1; cvt.u32.u64 %0, t; }"
        : "=r"(a) : "l"(p));
    return a;
}

#define CP_ASYNC16(dst, src) \
    asm volatile("cp.async.cg.shared.global [%0], [%1], 16;" \
                 :: "r"(dst), "l"(src) : "memory")
#define CP_ASYNC_COMMIT() asm volatile("cp.async.commit_group;" ::: "memory")
#define CP_ASYNC_WAIT1()  asm volatile("cp.async.wait_group 1;" ::: "memory")

#define LDSM_X4(r, addr) \
    asm volatile("ldmatrix.sync.aligned.m8n8.x4.shared.b16 {%0,%1,%2,%3}, [%4];" \
                 : "=r"((r)[0]), "=r"((r)[1]), "=r"((r)[2]), "=r"((r)[3]) \
                 : "r"(addr))

DEV_INLINE void mma16816(float* d, const uint32_t* a, const uint32_t* b) {
    asm volatile(
        "mma.sync.aligned.m16n8k16.row.col.f32.bf16.bf16.f32 "
        "{%0,%1,%2,%3}, {%4,%5,%6,%7}, {%8,%9}, {%0,%1,%2,%3};"
        : "+f"(d[0]), "+f"(d[1]), "+f"(d[2]), "+f"(d[3])
        : "r"(a[0]), "r"(a[1]), "r"(a[2]), "r"(a[3]),
          "r"(b[0]), "r"(b[1]));
}

// ---------------- packed f32x2 helpers (attention) --------------------------
DEV_INLINE unsigned long long pk2(float x, float y) {
    unsigned long long r;
    asm("mov.b64 %0, {%1, %2};" : "=l"(r)
        : "r"(__float_as_uint(x)), "r"(__float_as_uint(y)));
    return r;
}
DEV_INLINE void upk2(unsigned long long v, float &x, float &y) {
    unsigned int a, b;
    asm("mov.b64 {%0, %1}, %2;" : "=r"(a), "=r"(b) : "l"(v));
    x = __uint_as_float(a); y = __uint_as_float(b);
}
DEV_INLINE void fma2(unsigned long long &d, unsigned long long a, unsigned long long b) {
    asm("fma.rn.f32x2 %0, %1, %2, %0;" : "+l"(d) : "l"(a), "l"(b));
}
DEV_INLINE unsigned long long mul2(unsigned long long a, unsigned long long b) {
    unsigned long long r;
    asm("mul.rn.f32x2 %0, %1, %2;" : "=l"(r) : "l"(a), "l"(b));
    return r;
}

DEV_INLINE float gelu_exact(float x) {
    return 0.5f * x * (1.0f + erff(x * 0.7071067811865476f));
}

DEV_INLINE void split2(float x, float y, uint32_t &hi, uint32_t &lo) {
    __nv_bfloat162 h;
    h.x = __float2bfloat16(x);
    h.y = __float2bfloat16(y);
    __nv_bfloat162 l;
    l.x = __float2bfloat16(x - __bfloat162float(h.x));
    l.y = __float2bfloat16(y - __bfloat162float(h.y));
    hi = *(uint32_t*)&h;
    lo = *(uint32_t*)&l;
}

// ---------------- constants ----------------
#define MROWS 4096
#define HDIM  2048
#define FFDIM 8192

// ---------------- scratch -----------------------------------------------
__device__ __align__(16) __nv_bfloat16 g_actHi[MROWS * HDIM];
__device__ __align__(16) __nv_bfloat16 g_actLo[MROWS * HDIM];
__device__ __align__(16) __nv_bfloat16 g_ffnHi[MROWS * FFDIM];
__device__ __align__(16) __nv_bfloat16 g_ffnLo[MROWS * FFDIM];
__device__ __align__(16) float g_QKV[3 * MROWS * HDIM];
__device__ __align__(16) float g_h  [MROWS * HDIM];

__device__ __align__(16) __nv_bfloat16 g_wqTh[HDIM * HDIM],  g_wqTl[HDIM * HDIM];
__device__ __align__(16) __nv_bfloat16 g_wkTh[HDIM * HDIM],  g_wkTl[HDIM * HDIM];
__device__ __align__(16) __nv_bfloat16 g_wvTh[HDIM * HDIM],  g_wvTl[HDIM * HDIM];
__device__ __align__(16) __nv_bfloat16 g_woTh[HDIM * HDIM],  g_woTl[HDIM * HDIM];
__device__ __align__(16) __nv_bfloat16 g_w1Th[FFDIM * HDIM], g_w1Tl[FFDIM * HDIM];
__device__ __align__(16) __nv_bfloat16 g_w2Th[HDIM * FFDIM], g_w2Tl[HDIM * FFDIM];

// ================== weight transpose + split ================================
DEV_INLINE void transpose_body(
    const float* __restrict__ W, __nv_bfloat16* __restrict__ Th,
    __nv_bfloat16* __restrict__ Tl, int K, int N, int bx, int by)
{
    __shared__ float t[32][33];
    const int tx = threadIdx.x, ty = threadIdx.y;
    const int n0 = bx * 32, k0 = by * 32;
    #pragma unroll
    for (int i = 0; i < 4; i++)
        t[ty + i * 8][tx] = W[(size_t)(k0 + ty + i * 8) * N + n0 + tx];
    __syncthreads();
    #pragma unroll
    for (int i = 0; i < 4; i++) {
        float v = t[tx][ty + i * 8];
        __nv_bfloat16 h = __float2bfloat16(v);
        const size_t o = (size_t)(n0 + ty + i * 8) * K + k0 + tx;
        Th[o] = h;
        Tl[o] = __float2bfloat16(v - __bfloat162float(h));
    }
}

__global__ __launch_bounds__(256) void transpose_split(
    const float* __restrict__ W, __nv_bfloat16* __restrict__ Th,
    __nv_bfloat16* __restrict__ Tl, int K, int N)
{
    transpose_body(W, Th, Tl, K, N, blockIdx.x, blockIdx.y);
}

// fused transpose of 4 square HDIMxHDIM weights: blockIdx.z selects
__global__ __launch_bounds__(256) void transpose_split4(
    const float* __restrict__ W0, __nv_bfloat16* __restrict__ Th0, __nv_bfloat16* __restrict__ Tl0,
    const float* __restrict__ W1, __nv_bfloat16* __restrict__ Th1, __nv_bfloat16* __restrict__ Tl1,
    const float* __restrict__ W2, __nv_bfloat16* __restrict__ Th2, __nv_bfloat16* __restrict__ Tl2,
    const float* __restrict__ W3, __nv_bfloat16* __restrict__ Th3, __nv_bfloat16* __restrict__ Tl3)
{
    const int z = blockIdx.z;
    const float* W = (z == 0) ? W0 : (z == 1) ? W1 : (z == 2) ? W2 : W3;
    __nv_bfloat16* Th = (z == 0) ? Th0 : (z == 1) ? Th1 : (z == 2) ? Th2 : Th3;
    __nv_bfloat16* Tl = (z == 0) ? Tl0 : (z == 1) ? Tl1 : (z == 2) ? Tl2 : Tl3;
    transpose_body(W, Th, Tl, HDIM, HDIM, blockIdx.x, blockIdx.y);
}

// ================== mma.sync split-bf16 GEMM body ===========================
// Tile 128x128x32, 8 warps (2m x 4n), mma.m16n8k16 bf16, fp32 accum,
// 3 split terms.  smem: 64B rows, XOR swizzle.  3-stage cp.async, 2 CTA/SM.
// acc[4][4][4] keeps register use spill-free (empirically required).
// EPI: 0 = fp32 out, 1 = GELU -> bf16 hi/lo out, 2 = +residual fp32 out.
#define TILEB 8192
#define STAGEB (4 * TILEB)
#define NSTAGE 3
#define GM_SMEM_BYTES (NSTAGE * STAGEB)   // 98304

template<int EPI>
DEV_INLINE void gemm_body(
    const __nv_bfloat16* __restrict__ Ahi, const __nv_bfloat16* __restrict__ Alo,
    const __nv_bfloat16* __restrict__ Bhi, const __nv_bfloat16* __restrict__ Blo,
    const float* __restrict__ bias, const float* __restrict__ R,
    float* __restrict__ C, __nv_bfloat16* __restrict__ Chi,
    __nv_bfloat16* __restrict__ Clo, int N, int K, int bx, int by,
    uint32_t sb)
{
    const int tid = threadIdx.x;
    const int lane = tid & 31, wid = tid >> 5;
    const int wm = wid & 1, wn = wid >> 1;

    const __nv_bfloat16* gT[4] = {
        Ahi + (size_t)(by * 128) * K,
        Alo + (size_t)(by * 128) * K,
        Bhi + (size_t)(bx * 128) * K,
        Blo + (size_t)(bx * 128) * K };

    const int ld_r = tid >> 2, ld_c = tid & 3;

    auto issue = [&](int kb) {
        const uint32_t stg = sb + (kb % NSTAGE) * STAGEB;
        #pragma unroll
        for (int t = 0; t < 4; t++) {
            const __nv_bfloat16* g = gT[t];
            const uint32_t tb = stg + t * TILEB;
            #pragma unroll
            for (int i = 0; i < 2; i++) {
                const int r = ld_r + i * 64;
                const uint32_t dst = tb + r * 64 + ((ld_c ^ ((r >> 1) & 3)) * 16);
                CP_ASYNC16(dst, g + (size_t)r * K + kb * 32 + ld_c * 8);
            }
        }
    };

    float acc[4][4][4];
    #pragma unroll
    for (int mt = 0; mt < 4; mt++)
        #pragma unroll
        for (int nt = 0; nt < 4; nt++)
            #pragma unroll
            for (int r = 0; r < 4; r++) acc[mt][nt][r] = 0.0f;

    issue(0); CP_ASYNC_COMMIT();
    issue(1); CP_ASYNC_COMMIT();

    const int nkb = K >> 5;
    for (int kb = 0; kb < nkb; kb++) {
        CP_ASYNC_WAIT1();
        __syncthreads();
        if (kb + 2 < nkb) issue(kb + 2);
        CP_ASYNC_COMMIT();

        const uint32_t cur = sb + (kb % NSTAGE) * STAGEB;
        #pragma unroll
        for (int ks = 0; ks < 2; ks++) {
            // B fragments: one ldmatrix.x4 covers two n-tiles (lanes 16-31
            // address the second tile's rows)
            uint32_t bh[4][2], bl[4][2];
            #pragma unroll
            for (int ntp = 0; ntp < 2; ntp++) {
                const int r = wn * 32 + ntp * 16 + ((lane >> 4) & 1) * 8 + (lane & 7);
                const int ch = ks * 2 + ((lane >> 3) & 1);
                const uint32_t ba = cur + 2 * TILEB + r * 64
                                  + ((ch ^ ((r >> 1) & 3)) * 16);
                uint32_t t4[4];
                LDSM_X4(t4, ba);
                bh[ntp * 2][0] = t4[0]; bh[ntp * 2][1] = t4[1];
                bh[ntp * 2 + 1][0] = t4[2]; bh[ntp * 2 + 1][1] = t4[3];
                LDSM_X4(t4, ba + TILEB);
                bl[ntp * 2][0] = t4[0]; bl[ntp * 2][1] = t4[1];
                bl[ntp * 2 + 1][0] = t4[2]; bl[ntp * 2 + 1][1] = t4[3];
            }
            #pragma unroll
            for (int mt = 0; mt < 4; mt++) {
                uint32_t ah[4], al[4];
                const int r = wm * 64 + mt * 16 + (lane & 15);
                const int ch = ks * 2 + ((lane >> 4) & 1);
                const uint32_t aa = cur + r * 64
                                  + ((ch ^ ((r >> 1) & 3)) * 16);
                LDSM_X4(ah, aa);
                LDSM_X4(al, aa + TILEB);
                #pragma unroll
                for (int nt = 0; nt < 4; nt++) {
                    mma16816(acc[mt][nt], ah, bh[nt]);
                    mma16816(acc[mt][nt], ah, bl[nt]);
                    mma16816(acc[mt][nt], al, bh[nt]);
                }
            }
        }
    }

    // ---- epilogue ----
    #pragma unroll
    for (int mt = 0; mt < 4; mt++) {
        const int row = by * 128 + wm * 64 + mt * 16 + (lane >> 2);
        #pragma unroll
        for (int nt = 0; nt < 4; nt++) {
            const int col = bx * 128 + wn * 32 + nt * 8 + (lane & 3) * 2;
            float b0 = bias[col], b1 = bias[col + 1];
            float v0 = acc[mt][nt][0] + b0;
            float v1 = acc[mt][nt][1] + b1;
            float v2 = acc[mt][nt][2] + b0;
            float v3 = acc[mt][nt][3] + b1;
            const size_t o0 = (size_t)row * N + col;
            const size_t o1 = (size_t)(row + 8) * N + col;
            if (EPI == 1) {
                v0 = gelu_exact(v0); v1 = gelu_exact(v1);
                v2 = gelu_exact(v2); v3 = gelu_exact(v3);
                uint32_t h01, l01, h23, l23;
                split2(v0, v1, h01, l01);
                split2(v2, v3, h23, l23);
                *(uint32_t*)(Chi + o0) = h01;
                *(uint32_t*)(Clo + o0) = l01;
                *(uint32_t*)(Chi + o1) = h23;
                *(uint32_t*)(Clo + o1) = l23;
            } else {
                if (EPI == 2) {
                    float2 r0 = *(const float2*)(R + o0);
                    float2 r1 = *(const float2*)(R + o1);
                    v0 += r0.x; v1 += r0.y; v2 += r1.x; v3 += r1.y;
                }
                float2 s0; s0.x = v0; s0.y = v1;
                float2 s1; s1.x = v2; s1.y = v3;
                *(float2*)(C + o0) = s0;
                *(float2*)(C + o1) = s1;
            }
        }
    }
}

template<int EPI>
__global__ __launch_bounds__(256, 2) void gemm_mma(
    const __nv_bfloat16* __restrict__ Ahi, const __nv_bfloat16* __restrict__ Alo,
    const __nv_bfloat16* __restrict__ Bhi, const __nv_bfloat16* __restrict__ Blo,
    const float* __restrict__ bias, const float* __restrict__ R,
    float* __restrict__ C, __nv_bfloat16* __restrict__ Chi,
    __nv_bfloat16* __restrict__ Clo, int N, int K)
{
    extern __shared__ char smem[];
    gemm_body<EPI>(Ahi, Alo, Bhi, Blo, bias, R, C, Chi, Clo, N, K,
                   blockIdx.x, blockIdx.y, smem_u32(smem));
}

// fused QKV: grid (48, 32); blockIdx.x>>4 selects weight/bias/output
__global__ __launch_bounds__(256, 2) void gemm_qkv(
    const __nv_bfloat16* __restrict__ Ahi, const __nv_bfloat16* __restrict__ Alo,
    const __nv_bfloat16* __restrict__ Bh0, const __nv_bfloat16* __restrict__ Bl0,
    const __nv_bfloat16* __restrict__ Bh1, const __nv_bfloat16* __restrict__ Bl1,
    const __nv_bfloat16* __restrict__ Bh2, const __nv_bfloat16* __restrict__ Bl2,
    const float* __restrict__ b0, const float* __restrict__ b1,
    const float* __restrict__ b2, float* __restrict__ Cbase)
{
    extern __shared__ char smem[];
    const int sel = blockIdx.x >> 4;
    const int bx = blockIdx.x & 15;
    const __nv_bfloat16* Bh = (sel == 0) ? Bh0 : (sel == 1) ? Bh1 : Bh2;
    const __nv_bfloat16* Bl = (sel == 0) ? Bl0 : (sel == 1) ? Bl1 : Bl2;
    const float* bias = (sel == 0) ? b0 : (sel == 1) ? b1 : b2;
    float* C = Cbase + (size_t)sel * MROWS * HDIM;
    gemm_body<0>(Ahi, Alo, Bh, Bl, bias, nullptr, C, nullptr, nullptr,
                 HDIM, HDIM, bx, blockIdx.y, smem_u32(smem));
}

// ---------------- LayerNorm -> bf16 hi/lo -----------------------------------
__global__ __launch_bounds__(256) void ln_split(
    const float* __restrict__ x, const float* __restrict__ gamma,
    const float* __restrict__ beta,
    __nv_bfloat16* __restrict__ yh, __nv_bfloat16* __restrict__ yl)
{
    __shared__ float rs_[8], rq_[8];
    const int tid = threadIdx.x;
    const size_t row = blockIdx.x;
    const float4* xr = (const float4*)(x + row * HDIM);
    float4 v0 = xr[2 * tid];
    float4 v1 = xr[2 * tid + 1];
    float s = v0.x + v0.y + v0.z + v0.w + v1.x + v1.y + v1.z + v1.w;
    float q = v0.x*v0.x + v0.y*v0.y + v0.z*v0.z + v0.w*v0.w
            + v1.x*v1.x + v1.y*v1.y + v1.z*v1.z + v1.w*v1.w;
    #pragma unroll
    for (int o = 16; o; o >>= 1) {
        s += __shfl_xor_sync(0xffffffffu, s, o);
        q += __shfl_xor_sync(0xffffffffu, q, o);
    }
    if ((tid & 31) == 0) { rs_[tid >> 5] = s; rq_[tid >> 5] = q; }
    __syncthreads();
    s = 0.0f; q = 0.0f;
    #pragma unroll
    for (int i = 0; i < 8; i++) { s += rs_[i]; q += rq_[i]; }
    const float mean = s * (1.0f / 2048.0f);
    const float var  = q * (1.0f / 2048.0f) - mean * mean;
    const float rstd = rsqrtf(var + 1e-5f);
    const float4* gr = (const float4*)gamma;
    const float4* br = (const float4*)beta;
    float o[8];
    {
        float4 g4 = gr[2 * tid], b4 = br[2 * tid];
        o[0] = (v0.x - mean) * rstd * g4.x + b4.x;
        o[1] = (v0.y - mean) * rstd * g4.y + b4.y;
        o[2] = (v0.z - mean) * rstd * g4.z + b4.z;
        o[3] = (v0.w - mean) * rstd * g4.w + b4.w;
        g4 = gr[2 * tid + 1]; b4 = br[2 * tid + 1];
        o[4] = (v1.x - mean) * rstd * g4.x + b4.x;
        o[5] = (v1.y - mean) * rstd * g4.y + b4.y;
        o[6] = (v1.z - mean) * rstd * g4.z + b4.z;
        o[7] = (v1.w - mean) * rstd * g4.w + b4.w;
    }
    uint32_t h[4], l[4];
    split2(o[0], o[1], h[0], l[0]);
    split2(o[2], o[3], h[1], l[1]);
    split2(o[4], o[5], h[2], l[2]);
    split2(o[6], o[7], h[3], l[3]);
    uint4 hv; hv.x = h[0]; hv.y = h[1]; hv.z = h[2]; hv.w = h[3];
    uint4 lv; lv.x = l[0]; lv.y = l[1]; lv.z = l[2]; lv.w = l[3];
    *(uint4*)(yh + row * HDIM + tid * 8) = hv;
    *(uint4*)(yl + row * HDIM + tid * 8) = lv;
}

// ---------------- Causal flash attention (fp32 SIMT, bf16 hi/lo out) --------
#define ATTN_SMEM_FLOATS (128 * 65 + 128 * 64 + 64 * 128 + 64 * 65)
#define ATTN_SMEM_BYTES  (ATTN_SMEM_FLOATS * 4)

__global__ __launch_bounds__(256) void attn_kernel(
    const float* __restrict__ Qg, const float* __restrict__ Kg,
    const float* __restrict__ Vg,
    __nv_bfloat16* __restrict__ Ohi, __nv_bfloat16* __restrict__ Olo)
{
    extern __shared__ float sm[];
    float* Qt = sm;
    float* Kt = Qt + 128 * 65;
    float* Vs = Kt + 128 * 64;
    float* Pt = Vs + 64 * 128;

    const int tid = threadIdx.x;
    const int tx = tid & 15, ty = tid >> 4;
    // heavy q-tiles first: removes causal-imbalance tail in the last wave
    const int qt = gridDim.x - 1 - blockIdx.x;
    const int h = blockIdx.y, b = blockIdx.z;
    const size_t gbase = ((size_t)b * 2048) * HDIM + (size_t)h * 128;
    const int q0 = qt * 64;
    const float scale = 0.08838834764831845f;

    #pragma unroll
    for (int i = 0; i < 8; i++) {
        int f = i * 256 + tid;
        int qrow = f >> 5, d4 = f & 31;
        float4 v = *(const float4*)(Qg + gbase + (size_t)(q0 + qrow) * HDIM + d4 * 4);
        Qt[(d4 * 4 + 0) * 65 + qrow] = v.x;
        Qt[(d4 * 4 + 1) * 65 + qrow] = v.y;
        Qt[(d4 * 4 + 2) * 65 + qrow] = v.z;
        Qt[(d4 * 4 + 3) * 65 + qrow] = v.w;
    }

    unsigned long long o2[4][4];
    #pragma unroll
    for (int qi = 0; qi < 4; qi++)
        #pragma unroll
        for (int j = 0; j < 4; j++) o2[qi][j] = 0ULL;
    float m_[4], l_[4];
    #pragma unroll
    for (int qi = 0; qi < 4; qi++) { m_[qi] = -1e30f; l_[qi] = 0.0f; }

    for (int kt = 0; kt <= qt; kt++) {
        const int k0 = kt * 64;
        __syncthreads();
        #pragma unroll
        for (int i = 0; i < 8; i++) {
            int f = i * 256 + tid;
            int r = f >> 5, d4 = f & 31;
            float4 kv4 = *(const float4*)(Kg + gbase + (size_t)(k0 + r) * HDIM + d4 * 4);
            Kt[(d4 * 4 + 0) * 64 + r] = kv4.x;
            Kt[(d4 * 4 + 1) * 64 + r] = kv4.y;
            Kt[(d4 * 4 + 2) * 64 + r] = kv4.z;
            Kt[(d4 * 4 + 3) * 64 + r] = kv4.w;
            float4 vv4 = *(const float4*)(Vg + gbase + (size_t)(k0 + r) * HDIM + d4 * 4);
            *(float4*)&Vs[r * 128 + d4 * 4] = vv4;
        }
        __syncthreads();

        unsigned long long s2[4][2];
        #pragma unroll
        for (int qi = 0; qi < 4; qi++) { s2[qi][0] = 0ULL; s2[qi][1] = 0ULL; }
        #pragma unroll 4
        for (int d = 0; d < 128; d++) {
            float4 kb = *(const float4*)&Kt[d * 64 + tx * 4];
            unsigned long long kp0 = pk2(kb.x, kb.y);
            unsigned long long kp1 = pk2(kb.z, kb.w);
            #pragma unroll
            for (int qi = 0; qi < 4; qi++) {
                float a = Qt[d * 65 + ty * 4 + qi];
                unsigned long long ap = pk2(a, a);
                fma2(s2[qi][0], ap, kp0);
                fma2(s2[qi][1], ap, kp1);
            }
        }
        float sv[4][4];
        #pragma unroll
        for (int qi = 0; qi < 4; qi++) {
            upk2(s2[qi][0], sv[qi][0], sv[qi][1]);
            upk2(s2[qi][1], sv[qi][2], sv[qi][3]);
        }
        #pragma unroll
        for (int qi = 0; qi < 4; qi++)
            #pragma unroll
            for (int ki = 0; ki < 4; ki++) {
                float val = sv[qi][ki] * scale;
                if (kt == qt && (k0 + tx * 4 + ki) > (q0 + ty * 4 + qi))
                    val = -1e30f;
                sv[qi][ki] = val;
            }
        float mt[4];
        #pragma unroll
        for (int qi = 0; qi < 4; qi++)
            mt[qi] = fmaxf(fmaxf(sv[qi][0], sv[qi][1]), fmaxf(sv[qi][2], sv[qi][3]));
        #pragma unroll
        for (int o = 1; o < 16; o <<= 1)
            #pragma unroll
            for (int qi = 0; qi < 4; qi++)
                mt[qi] = fmaxf(mt[qi], __shfl_xor_sync(0xffffffffu, mt[qi], o));
        float rs[4], alpha[4];
        #pragma unroll
        for (int qi = 0; qi < 4; qi++) {
            float mn = fmaxf(m_[qi], mt[qi]);
            alpha[qi] = __expf(m_[qi] - mn);
            float r = 0.0f;
            #pragma unroll
            for (int ki = 0; ki < 4; ki++) {
                float p = __expf(sv[qi][ki] - mn);
                sv[qi][ki] = p;
                r += p;
            }
            rs[qi] = r;
            m_[qi] = mn;
        }
        #pragma unroll
        for (int o = 1; o < 16; o <<= 1)
            #pragma unroll
            for (int qi = 0; qi < 4; qi++)
                rs[qi] += __shfl_xor_sync(0xffffffffu, rs[qi], o);
        #pragma unroll
        for (int qi = 0; qi < 4; qi++) {
            l_[qi] = l_[qi] * alpha[qi] + rs[qi];
            unsigned long long alp = pk2(alpha[qi], alpha[qi]);
            #pragma unroll
            for (int j = 0; j < 4; j++) o2[qi][j] = mul2(o2[qi][j], alp);
        }
        #pragma unroll
        for (int qi = 0; qi < 4; qi++)
            #pragma unroll
            for (int ki = 0; ki < 4; ki++)
                Pt[(tx * 4 + ki) * 65 + ty * 4 + qi] = sv[qi][ki];
        __syncthreads();
        #pragma unroll 2
        for (int kv = 0; kv < 64; kv++) {
            float4 v0 = *(const float4*)&Vs[kv * 128 + tx * 8];
            float4 v1 = *(const float4*)&Vs[kv * 128 + tx * 8 + 4];
            unsigned long long vp[4] = { pk2(v0.x, v0.y), pk2(v0.z, v0.w),
                                         pk2(v1.x, v1.y), pk2(v1.z, v1.w) };
            #pragma unroll
            for (int qi = 0; qi < 4; qi++) {
                float p = Pt[kv * 65 + ty * 4 + qi];
                unsigned long long pp = pk2(p, p);
                #pragma unroll
                for (int j = 0; j < 4; j++) fma2(o2[qi][j], pp, vp[j]);
            }
        }
    }
    #pragma unroll
    for (int qi = 0; qi < 4; qi++) {
        float inv = 1.0f / l_[qi];
        unsigned long long ip = pk2(inv, inv);
        float ov[8];
        #pragma unroll
        for (int j = 0; j < 4; j++) {
            o2[qi][j] = mul2(o2[qi][j], ip);
            upk2(o2[qi][j], ov[2 * j], ov[2 * j + 1]);
        }
        uint32_t hh[4], ll[4];
        split2(ov[0], ov[1], hh[0], ll[0]);
        split2(ov[2], ov[3], hh[1], ll[1]);
        split2(ov[4], ov[5], hh[2], ll[2]);
        split2(ov[6], ov[7], hh[3], ll[3]);
        const int qrow = q0 + ty * 4 + qi;
        const size_t oo = gbase + (size_t)qrow * HDIM + tx * 8;
        uint4 hv; hv.x = hh[0]; hv.y = hh[1]; hv.z = hh[2]; hv.w = hh[3];
        uint4 lv; lv.x = ll[0]; lv.y = ll[1]; lv.z = ll[2]; lv.w = ll[3];
        *(uint4*)(Ohi + oo) = hv;
        *(uint4*)(Olo + oo) = lv;
    }
}

// ---------------- launch --------------------------------------------------
extern "C" void kernel_launch(void* const* d_in, const int* in_sizes, int n_in,
                              void* d_out, int out_size)
{
    (void)in_sizes; (void)n_in; (void)out_size;
    const float* x   = (const float*)d_in[0];
    const float* wq  = (const float*)d_in[1];
    const float* bq  = (const float*)d_in[2];
    const float* wk  = (const float*)d_in[3];
    const float* bk  = (const float*)d_in[4];
    const float* wv  = (const float*)d_in[5];
    const float* bv  = (const float*)d_in[6];
    const float* wo  = (const float*)d_in[7];
    const float* bo  = (const float*)d_in[8];
    const float* g1  = (const float*)d_in[9];
    const float* be1 = (const float*)d_in[10];
    const float* g2  = (const float*)d_in[11];
    const float* be2 = (const float*)d_in[12];
    const float* w1  = (const float*)d_in[13];
    const float* b1  = (const float*)d_in[14];
    const float* w2  = (const float*)d_in[15];
    const float* b2  = (const float*)d_in[16];
    float* out = (float*)d_out;

    __nv_bfloat16 *actHi, *actLo, *ffnHi, *ffnLo;
    float *p_QKV, *p_h;
    cudaGetSymbolAddress((void**)&actHi, g_actHi);
    cudaGetSymbolAddress((void**)&actLo, g_actLo);
    cudaGetSymbolAddress((void**)&ffnHi, g_ffnHi);
    cudaGetSymbolAddress((void**)&ffnLo, g_ffnLo);
    cudaGetSymbolAddress((void**)&p_QKV, g_QKV);
    cudaGetSymbolAddress((void**)&p_h,   g_h);

    __nv_bfloat16 *wqTh, *wqTl, *wkTh, *wkTl, *wvTh, *wvTl, *woTh, *woTl;
    __nv_bfloat16 *w1Th, *w1Tl, *w2Th, *w2Tl;
    cudaGetSymbolAddress((void**)&wqTh, g_wqTh);
    cudaGetSymbolAddress((void**)&wqTl, g_wqTl);
    cudaGetSymbolAddress((void**)&wkTh, g_wkTh);
    cudaGetSymbolAddress((void**)&wkTl, g_wkTl);
    cudaGetSymbolAddress((void**)&wvTh, g_wvTh);
    cudaGetSymbolAddress((void**)&wvTl, g_wvTl);
    cudaGetSymbolAddress((void**)&woTh, g_woTh);
    cudaGetSymbolAddress((void**)&woTl, g_woTl);
    cudaGetSymbolAddress((void**)&w1Th, g_w1Th);
    cudaGetSymbolAddress((void**)&w1Tl, g_w1Tl);
    cudaGetSymbolAddress((void**)&w2Th, g_w2Th);
    cudaGetSymbolAddress((void**)&w2Tl, g_w2Tl);

    float* p_q = p_QKV;
    float* p_k = p_QKV + (size_t)MROWS * HDIM;
    float* p_v = p_QKV + (size_t)2 * MROWS * HDIM;

    cudaFuncSetAttribute(attn_kernel,
                         cudaFuncAttributeMaxDynamicSharedMemorySize,
                         ATTN_SMEM_BYTES);
    cudaFuncSetAttribute(gemm_mma<0>,
                         cudaFuncAttributeMaxDynamicSharedMemorySize, GM_SMEM_BYTES);
    cudaFuncSetAttribute(gemm_mma<1>,
                         cudaFuncAttributeMaxDynamicSharedMemorySize, GM_SMEM_BYTES);
    cudaFuncSetAttribute(gemm_mma<2>,
                         cudaFuncAttributeMaxDynamicSharedMemorySize, GM_SMEM_BYTES);
    cudaFuncSetAttribute(gemm_qkv,
                         cudaFuncAttributeMaxDynamicSharedMemorySize, GM_SMEM_BYTES);

    const dim3 tb(32, 8);

    ln_split<<<MROWS, 256>>>(x, g1, be1, actHi, actLo);

    // fused transpose of wq/wk/wv/wo (one launch, blockIdx.z selects)
    transpose_split4<<<dim3(HDIM / 32, HDIM / 32, 4), tb>>>(
        wq, wqTh, wqTl, wk, wkTh, wkTl, wv, wvTh, wvTl, wo, woTh, woTl);

    // fused QKV projection
    gemm_qkv<<<dim3(48, 32), 256, GM_SMEM_BYTES>>>(
        actHi, actLo, wqTh, wqTl, wkTh, wkTl, wvTh, wvTl, bq, bk, bv, p_QKV);

    // causal attention -> split output (overwrites LN1 act, now dead)
    attn_kernel<<<dim3(32, 16, 2), 256, ATTN_SMEM_BYTES>>>(p_q, p_k, p_v, actHi, actLo);

    // output projection + residual (h = x + attn @ wo + bo)
    gemm_mma<2><<<dim3(16, 32), 256, GM_SMEM_BYTES>>>(actHi, actLo, woTh, woTl, bo, x, p_h, nullptr, nullptr, HDIM, HDIM);

    // LN2 -> split (attn act dead)
    ln_split<<<MROWS, 256>>>(p_h, g2, be2, actHi, actLo);

    // FFN weight transposes (deferred)
    transpose_split<<<dim3(FFDIM / 32, HDIM / 32), tb>>>(w1, w1Th, w1Tl, HDIM, FFDIM);
    transpose_split<<<dim3(HDIM / 32, FFDIM / 32), tb>>>(w2, w2Th, w2Tl, FFDIM, HDIM);

    // FFN1 + GELU -> split output
    gemm_mma<1><<<dim3(64, 32), 256, GM_SMEM_BYTES>>>(actHi, actLo, w1Th, w1Tl, b1, nullptr, nullptr, ffnHi, ffnLo, FFDIM, HDIM);

    // FFN2 + residual -> final output
    gemm_mma<2><<<dim3(16, 32), 256, GM_SMEM_BYTES>>>(ffnHi, ffnLo, w2Th, w2Tl, b2, p_h, out, nullptr, nullptr, HDIM, FFDIM);
}